// round 16
// baseline (speedup 1.0000x reference)
#include <cuda_runtime.h>
#include <cuda_fp16.h>
#include <stdint.h>

#define B_   16
#define CIN  512
#define COUT 512
#define HS   36
#define WS   36
#define HO   38   // conv output spatial

#define XP_STRIDE 1764   // padded x map: 42 rows x 42 cols (halo -2..39), u32(half2) units
#define XT_S      264    // k4 x-tile pair-row stride in u32 (264 % 32 == 8 -> bank-safe)
#define XTILE_U   2112   // 8 pair-rows * XT_S (6 rows x 42 used per pair-row)
#define WTILE_U   4608   // 9 taps * 512 (64 o * 8 kpidx)
#define STAGE_U   (XTILE_U + WTILE_U)          // 6720 u32 per stage
#define K4_SMEM   (2 * STAGE_U * 4)            // 53760 bytes

// ---------------- device scratch (no allocation allowed) ----------------
__device__ float g_sn[B_ * CIN];
__device__ float g_bb[B_ * COUT];
__device__ float g_g[B_ * COUT];
__device__ float g_wscale[COUT];
__device__ float g_rawsq[COUT * CIN];
__device__ float g_a[(size_t)B_ * COUT * HO * HO];          // conv out + bias (47MB)
__device__ uint32_t g_xh[(size_t)B_ * 256 * XP_STRIDE];     // half2(x*sn) padded (28.9MB)
__device__ uint32_t g_wh2[(size_t)8 * 32 * 9 * 512];        // half2 weights, mma layout (4.7MB)

__inline__ __device__ float warpReduceSum(float v) {
    #pragma unroll
    for (int off = 16; off; off >>= 1) v += __shfl_xor_sync(0xffffffffu, v, off);
    return v;
}

__device__ __forceinline__ void mma_f16(float c[4], uint32_t a0, uint32_t a1,
                                        uint32_t a2, uint32_t a3,
                                        uint32_t b0, uint32_t b1) {
    asm volatile(
        "mma.sync.aligned.m16n8k16.row.col.f32.f16.f16.f32 "
        "{%0,%1,%2,%3}, {%4,%5,%6,%7}, {%8,%9}, {%0,%1,%2,%3};\n"
        : "+f"(c[0]), "+f"(c[1]), "+f"(c[2]), "+f"(c[3])
        : "r"(a0), "r"(a1), "r"(a2), "r"(a3), "r"(b0), "r"(b1));
}

__device__ __forceinline__ void cp_async16(uint32_t s, const void* g) {
    asm volatile("cp.async.cg.shared.global [%0], [%1], 16;" :: "r"(s), "l"(g));
}

// ---------------- K1: styles s, normalized sn, modulated bias bb --------
__global__ void k1_style(const float* __restrict__ w, const float* __restrict__ msg,
                         const float* __restrict__ aw, const float* __restrict__ ab,
                         const float* __restrict__ bias, const float* __restrict__ msw,
                         const float* __restrict__ mbw) {
    int b = blockIdx.x;
    __shared__ float wsh[CIN];
    __shared__ float msh[64];
    __shared__ float ssh[CIN];
    __shared__ float red[16];
    int tid = threadIdx.x;
    wsh[tid] = w[b * CIN + tid];
    if (tid < 64) msh[tid] = msg[b * 64 + tid];
    __syncthreads();
    int warp = tid >> 5, lane = tid & 31;
    #pragma unroll 1
    for (int ii = 0; ii < 32; ii++) {
        int i = warp * 32 + ii;
        const float* ar = aw + (size_t)i * CIN;
        float acc = 0.f;
        for (int j = lane; j < CIN; j += 32) acc += wsh[j] * ar[j];
        float accm = 0.f;
        for (int m = lane; m < 64; m += 32) accm += msh[m] * msw[m * CIN + i];
        float v = warpReduceSum(acc + 0.01f * accm);
        if (lane == 0) ssh[i] = v + ab[i];
    }
    __syncthreads();
    float sv = ssh[tid];
    float ss = warpReduceSum(sv * sv);
    if (lane == 0) red[warp] = ss;
    __syncthreads();
    if (warp == 0) {
        float t = (lane < 16) ? red[lane] : 0.f;
        t = warpReduceSum(t);
        if (lane == 0) red[0] = t;
    }
    __syncthreads();
    g_sn[b * CIN + tid] = sv * rsqrtf(red[0] * (1.f / CIN));
    float bacc = 0.f;
    #pragma unroll 8
    for (int m = 0; m < 64; m++) bacc += msh[m] * mbw[m * COUT + tid];
    g_bb[b * COUT + tid] = bias[tid] + 0.01f * bacc;
}

// ---------------- K2: weight norms + half2 mma-layout rewrite ----------
// (absorbs old k0_prew: both stream the same weight rows; L1-warm reuse)
__global__ void k2_wnorm(const float* __restrict__ weight) {
    int o = blockIdx.x, tid = threadIdx.x;
    float tot = 0.f;
    for (int i = tid; i < CIN; i += 256) {
        const float* wp = weight + ((size_t)o * CIN + i) * 9;
        float sq = 0.f;
        #pragma unroll
        for (int k = 0; k < 9; k++) sq += wp[k] * wp[k];
        g_rawsq[o * CIN + i] = sq;
        tot += sq;
    }
    __shared__ float red[8];
    int warp = tid >> 5, lane = tid & 31;
    tot = warpReduceSum(tot);
    if (lane == 0) red[warp] = tot;
    __syncthreads();
    if (warp == 0) {
        float t = (lane < 8) ? red[lane] : 0.f;
        t = warpReduceSum(t);
        if (lane == 0) g_wscale[o] = rsqrtf(t * (1.f / (CIN * 9)));
    }
    // ---- half2 weight rewrite for this o: 256 pairs x 9 taps ----
    const int obase_sl = (o >> 6) * 32;      // otile*32 chunks
    const int oslot = (o & 63) * 8;
    for (int e = tid; e < 256 * 9; e += 256) {
        int tap = e % 9;
        int kp = e / 9;                      // global channel pair 0..255
        int chunk = kp >> 3, kpl = kp & 7;
        int kpidx = (kpl & 3) * 2 + (kpl >> 2);
        size_t s0 = ((size_t)o * CIN + kp * 2) * 9 + tap;
        __half2 h = __floats2half2_rn(weight[s0], weight[s0 + 9]);
        size_t dst = (((size_t)(obase_sl + chunk) * 9 + tap) * 512) + oslot + kpidx;
        g_wh2[dst] = *(uint32_t*)&h;
    }
}

// ---------------- K3: demod scale g[b,o] ----------------
__global__ void k3_demod(const float* __restrict__ mag) {
    int o = blockIdx.x, b = blockIdx.y, tid = threadIdx.x;
    float acc = 0.f;
    for (int i = tid; i < CIN; i += 128) {
        float s = g_sn[b * CIN + i];
        acc += g_rawsq[o * CIN + i] * s * s;
    }
    __shared__ float red[4];
    int warp = tid >> 5, lane = tid & 31;
    acc = warpReduceSum(acc);
    if (lane == 0) red[warp] = acc;
    __syncthreads();
    if (tid == 0) {
        float t = red[0] + red[1] + red[2] + red[3];
        float wsc = g_wscale[o];
        float d = rsqrtf(wsc * wsc * t + 1e-8f);
        g_g[b * COUT + o] = d * wsc * rsqrtf(mag[0]);
    }
}

// ---------------- K0x: padded half2(x*sn), halo zeros baked in --------
__global__ void k0_prex(const float* __restrict__ x) {
    const size_t N = (size_t)B_ * 256 * XP_STRIDE;
    for (size_t e = (size_t)blockIdx.x * 256 + threadIdx.x; e < N;
         e += (size_t)gridDim.x * 256) {
        int p = (int)(e % XP_STRIDE);
        int mp = (int)(e / XP_STRIDE);
        int b = mp >> 8, pairIdx = mp & 255;
        int c0 = pairIdx * 2;
        int prg = p / 42, pc = p - prg * 42;
        int gr = prg - 2, gq = pc - 2;
        float v0 = 0.f, v1 = 0.f;
        if ((unsigned)gr < HS && (unsigned)gq < WS) {
            size_t sidx = (((size_t)b * CIN + c0) * HS + gr) * WS + gq;
            v0 = x[sidx] * g_sn[b * CIN + c0];
            v1 = x[sidx + (size_t)HS * WS] * g_sn[b * CIN + c0 + 1];
        }
        __half2 h = __floats2half2_rn(v0, v1);
        g_xh[e] = *(uint32_t*)&h;
    }
}

// ---------------- K4: fp16 m16n8k16 conv, cp.async double-buffered ----
// grid = (8 o-tiles, 10 r-tiles of 4 rows, 16 b), block = 128 (4 warps), occ 4
// Warps whose both rows are >= HO skip all mma issue (5% tensor-pipe savings).
__global__ __launch_bounds__(128, 4) void k4_mma() {
    extern __shared__ uint32_t dsm[];
    const int b  = blockIdx.z;
    const int o0 = blockIdx.x * 64;
    const int r0 = blockIdx.y * 4;

    const int tid  = threadIdx.x;
    const int lane = tid & 31;
    const int wrp  = tid >> 5;
    const int ob   = (wrp & 1) * 32;    // warp o-offset
    const int pr0  = (wrp >> 1) * 2;    // warp row-offset (0,2)
    const int ln4  = lane >> 2;
    const int lk   = lane & 3;
    const bool live = (r0 + pr0 < HO);  // rows pr0, pr0+1 both dead when false

    float c[2][10][4];
    #pragma unroll
    for (int s = 0; s < 2; s++)
        #pragma unroll
        for (int f = 0; f < 10; f++)
            #pragma unroll
            for (int j = 0; j < 4; j++) c[s][f][j] = 0.f;

    const uint32_t* xsrc = g_xh + (size_t)(b * 256) * XP_STRIDE + r0 * 42;
    const uint32_t* wsrc0 = g_wh2 + (size_t)blockIdx.x * 32 * 9 * 512;
    const uint32_t sbase = (uint32_t)__cvta_generic_to_shared(dsm);

    auto issue = [&](int chunk, int stage) {
        const uint32_t xs = sbase + (uint32_t)stage * (STAGE_U * 4);
        const uint32_t wsb = xs + XTILE_U * 4;
        const uint32_t* sx = xsrc + (size_t)chunk * 8 * XP_STRIDE;
        #pragma unroll
        for (int it = 0; it < 4; it++) {
            int e = tid + it * 128;
            if (e < 504) {
                int pr = e / 63, j = e - pr * 63;
                cp_async16(xs + (uint32_t)(pr * XT_S + 4 * j) * 4,
                           sx + (size_t)pr * XP_STRIDE + 4 * j);
            }
        }
        const uint32_t* sw = wsrc0 + (size_t)chunk * (9 * 512);
        #pragma unroll
        for (int it = 0; it < 9; it++) {
            int e = tid + it * 128;
            cp_async16(wsb + (uint32_t)e * 16, sw + (size_t)e * 4);
        }
        asm volatile("cp.async.commit_group;");
    };

    issue(0, 0);
    issue(1, 1);

    for (int i = 0; i < 32; i++) {
        if (i < 30) asm volatile("cp.async.wait_group 1;");
        else        asm volatile("cp.async.wait_group 0;");
        __syncthreads();
        const uint32_t* xsm = dsm + (i & 1) * STAGE_U;
        const uint32_t* wsm = xsm + XTILE_U;

        if (live) {
            #pragma unroll
            for (int ky = 0; ky < 3; ky++) {
                #pragma unroll
                for (int kx = 0; kx < 3; kx++) {
                    const int tap = ky * 3 + kx;
                    uint2 a_lo[2], a_hi[2];
                    #pragma unroll
                    for (int s = 0; s < 2; s++) {
                        const uint32_t* wp = wsm + tap * 512 + (ob + s * 16 + ln4) * 8 + lk * 2;
                        a_lo[s] = *(const uint2*)wp;          // rows +0: (a0, a2)
                        a_hi[s] = *(const uint2*)(wp + 64);   // rows +8: (a1, a3)
                    }
                    #pragma unroll
                    for (int f = 0; f < 10; f++) {
                        const int pr = pr0 + (f >= 5 ? 1 : 0);
                        const int cg = (f >= 5 ? f - 5 : f);
                        const int idx = (pr + ky) * 42 + cg * 8 + ln4 + kx;
                        uint32_t b0 = xsm[lk * XT_S + idx];
                        uint32_t b1 = xsm[(lk + 4) * XT_S + idx];
                        mma_f16(c[0][f], a_lo[0].x, a_hi[0].x, a_lo[0].y, a_hi[0].y, b0, b1);
                        mma_f16(c[1][f], a_lo[1].x, a_hi[1].x, a_lo[1].y, a_hi[1].y, b0, b1);
                    }
                }
            }
        }
        __syncthreads();
        if (i + 2 < 32) issue(i + 2, i & 1);
    }

    if (live) {
        const int n0 = lk * 2;
        #pragma unroll
        for (int s = 0; s < 2; s++) {
            #pragma unroll
            for (int rh = 0; rh < 2; rh++) {
                const int o = o0 + ob + s * 16 + ln4 + rh * 8;
                const float gg = g_g[b * COUT + o];
                const float bb = g_bb[b * COUT + o];
                float* abase = g_a + ((size_t)(b * COUT + o)) * (HO * HO);
                #pragma unroll
                for (int f = 0; f < 10; f++) {
                    const int r = r0 + pr0 + (f >= 5 ? 1 : 0);
                    if (r >= HO) continue;
                    const int cg = (f >= 5 ? f - 5 : f);
                    const int q = cg * 8 + n0;
                    float* ap = abase + r * HO;
                    float v0 = c[s][f][rh * 2 + 0] * gg + bb;
                    float v1 = c[s][f][rh * 2 + 1] * gg + bb;
                    if (q < HO)     ap[q]     = v0;
                    if (q + 1 < HO) ap[q + 1] = v1;
                }
            }
        }
    }
}

// ---------------- K5: fused filtered_lrelu (register-windowed) ----------
#define SB_APAD 0
#define SB_VPAD (46 * 38)
#define SB_Z    (46 * 38 + 82 * 46)
#define SB_TOT  (46 * 38 + 82 * 46 + 82 * 82)   // 12244 floats = 48976 B

__global__ __launch_bounds__(256) void k5_flrelu(const float* __restrict__ fup,
                                                 const float* __restrict__ fdn,
                                                 float* __restrict__ out) {
    const int map = blockIdx.x;
    __shared__ float sb[SB_TOT];
    float* Apad = sb + SB_APAD;   // 46 x 38
    float* Vpad = sb + SB_VPAD;   // 82 x 46
    float* Z    = sb + SB_Z;      // 82 x 82
    float* T    = sb;             // 36 x 82 (aliases Apad+Vpad, dead by then)
    const int tid = threadIdx.x;

    float fu[12], fd[12];
    #pragma unroll
    for (int s = 0; s < 12; s++) { fu[s] = fup[s] * 2.f; fd[s] = fdn[s]; }

    for (int i = tid; i < SB_Z; i += 256) sb[i] = 0.f;    // zero Apad+Vpad
    __syncthreads();
    const float* ap = g_a + (size_t)map * HO * HO;
    for (int i = tid; i < HO * HO; i += 256) {
        int r = i / HO, q = i - r * HO;
        Apad[(r + 4) * 38 + q] = ap[i];
    }
    __syncthreads();

    // ---- Vup: 228 threads, j = col, 14 u-rows per thread ----
    if (tid < 228) {
        const int j = tid % 38, ub = tid / 38;
        const int u0 = ub * 14;            // even
        const int a0 = u0 >> 1;
        float win[13];
        #pragma unroll
        for (int i = 0; i < 13; i++)
            win[i] = (a0 + i < 46) ? Apad[(a0 + i) * 38 + j] : 0.f;
        #pragma unroll
        for (int du = 0; du < 14; du++) {
            int u = u0 + du;
            if (u < 82) {
                const int ph = du & 1;
                float acc = 0.f;
                #pragma unroll
                for (int sg = 0; sg < 6; sg++)
                    acc += fu[2 * sg + ph] * win[(du >> 1) + 5 - sg];
                Vpad[u * 46 + (j + 4)] = acc;
            }
        }
    }
    __syncthreads();

    // ---- Hup + lrelu + clamp: 246 threads, u = row, 28 xq per thread ----
    if (tid < 246) {
        const int u = tid % 82, xb = tid / 82;
        const int x0 = xb * 28;            // even
        const int cb = x0 >> 1;
        float win[19];
        #pragma unroll
        for (int i = 0; i < 19; i++)
            win[i] = (cb + i < 46) ? Vpad[u * 46 + cb + i] : 0.f;
        #pragma unroll
        for (int dx = 0; dx < 28; dx++) {
            int xq = x0 + dx;
            if (xq < 82) {
                const int ph = dx & 1;
                float acc = 0.f;
                #pragma unroll
                for (int sg = 0; sg < 6; sg++)
                    acc += fu[2 * sg + ph] * win[(dx >> 1) + 5 - sg];
                acc = (acc >= 0.f) ? acc : 0.2f * acc;
                acc *= 1.4142135623730951f;
                acc = fminf(fmaxf(acc, -256.f), 256.f);
                Z[u * 82 + xq] = acc;
            }
        }
    }
    __syncthreads();

    // ---- Vdown: 246 threads, xq = col, 12 r per thread ----
    if (tid < 246) {
        const int xq = tid % 82, rb = tid / 82;
        const int r0 = rb * 12;
        const int z0 = 2 * r0;
        float wz[34];
        #pragma unroll
        for (int i = 0; i < 34; i++)
            wz[i] = Z[(z0 + i) * 82 + xq];
        #pragma unroll
        for (int dr = 0; dr < 12; dr++) {
            float acc = 0.f;
            #pragma unroll
            for (int s = 0; s < 12; s++)
                acc += fd[s] * wz[2 * dr + 11 - s];
            T[(r0 + dr) * 82 + xq] = acc;
        }
    }
    __syncthreads();

    // ---- Hdown: 216 threads, r = row, 6 c per thread ----
    if (tid < 216) {
        const int r = tid % 36, cbk = tid / 36;
        const int c0 = cbk * 6;
        float wt[22];
        #pragma unroll
        for (int i = 0; i < 22; i++)
            wt[i] = T[r * 82 + 2 * c0 + i];
        float* op = out + (size_t)map * 36 * 36 + r * 36;
        #pragma unroll
        for (int dc = 0; dc < 6; dc++) {
            float acc = 0.f;
            #pragma unroll
            for (int s = 0; s < 12; s++)
                acc += fd[s] * wt[2 * dc + 11 - s];
            op[c0 + dc] = acc;
        }
    }
}

// ---------------- launch ----------------
extern "C" void kernel_launch(void* const* d_in, const int* in_sizes, int n_in,
                              void* d_out, int out_size) {
    const float* x    = (const float*)d_in[0];
    const float* w    = (const float*)d_in[1];
    const float* msg  = (const float*)d_in[2];
    const float* aw   = (const float*)d_in[3];
    const float* ab   = (const float*)d_in[4];
    const float* wgt  = (const float*)d_in[5];
    const float* bias = (const float*)d_in[6];
    const float* msw  = (const float*)d_in[7];
    const float* mbw  = (const float*)d_in[8];
    const float* fup  = (const float*)d_in[9];
    const float* fdn  = (const float*)d_in[10];
    const float* mag  = (const float*)d_in[11];
    float* out = (float*)d_out;

    cudaFuncSetAttribute(k4_mma, cudaFuncAttributeMaxDynamicSharedMemorySize, K4_SMEM);

    k1_style<<<B_, 512>>>(w, msg, aw, ab, bias, msw, mbw);
    k2_wnorm<<<COUT, 256>>>(wgt);
    k3_demod<<<dim3(COUT, B_), 128>>>(mag);
    k0_prex<<<8192, 256>>>(x);
    k4_mma<<<dim3(8, 10, B_), 128, K4_SMEM>>>();
    k5_flrelu<<<B_ * COUT, 256>>>(fup, fdn, out);
}

// round 17
// speedup vs baseline: 1.0130x; 1.0130x over previous
#include <cuda_runtime.h>
#include <cuda_fp16.h>
#include <stdint.h>

#define B_   16
#define CIN  512
#define COUT 512
#define HS   36
#define WS   36
#define HO   38   // conv output spatial

#define XP_STRIDE 1764   // padded x map: 42 rows x 42 cols (halo -2..39), u32(half2) units
#define XT_S      264    // k4 x-tile pair-row stride in u32 (264 % 32 == 8 -> bank-safe)
#define XTILE_U   2112   // 8 pair-rows * XT_S (6 rows x 42 used per pair-row)
#define WTILE_U   4608   // 9 taps * 512 (64 o * 8 kpidx)
#define STAGE_U   (XTILE_U + WTILE_U)          // 6720 u32 per stage
#define K4_SMEM   (2 * STAGE_U * 4)            // 53760 bytes

// ---------------- device scratch (no allocation allowed) ----------------
__device__ float g_sn[B_ * CIN];
__device__ float g_bb[B_ * COUT];
__device__ float g_g[B_ * COUT];
__device__ float g_wscale[COUT];
__device__ float g_rawsq[COUT * CIN];
__device__ float g_a[(size_t)B_ * COUT * HO * HO];          // conv out + bias (47MB)
__device__ uint32_t g_xh[(size_t)B_ * 256 * XP_STRIDE];     // half2(x*sn) padded (28.9MB)
__device__ uint32_t g_wh2[(size_t)8 * 32 * 9 * 512];        // half2 weights, mma layout (4.7MB)

__inline__ __device__ float warpReduceSum(float v) {
    #pragma unroll
    for (int off = 16; off; off >>= 1) v += __shfl_xor_sync(0xffffffffu, v, off);
    return v;
}

__device__ __forceinline__ void mma_f16(float c[4], uint32_t a0, uint32_t a1,
                                        uint32_t a2, uint32_t a3,
                                        uint32_t b0, uint32_t b1) {
    asm volatile(
        "mma.sync.aligned.m16n8k16.row.col.f32.f16.f16.f32 "
        "{%0,%1,%2,%3}, {%4,%5,%6,%7}, {%8,%9}, {%0,%1,%2,%3};\n"
        : "+f"(c[0]), "+f"(c[1]), "+f"(c[2]), "+f"(c[3])
        : "r"(a0), "r"(a1), "r"(a2), "r"(a3), "r"(b0), "r"(b1));
}

__device__ __forceinline__ void cp_async16(uint32_t s, const void* g) {
    asm volatile("cp.async.cg.shared.global [%0], [%1], 16;" :: "r"(s), "l"(g));
}

// ---------------- K1: styles s, normalized sn, modulated bias bb --------
__global__ void k1_style(const float* __restrict__ w, const float* __restrict__ msg,
                         const float* __restrict__ aw, const float* __restrict__ ab,
                         const float* __restrict__ bias, const float* __restrict__ msw,
                         const float* __restrict__ mbw) {
    int b = blockIdx.x;
    __shared__ float wsh[CIN];
    __shared__ float msh[64];
    __shared__ float ssh[CIN];
    __shared__ float red[16];
    int tid = threadIdx.x;
    wsh[tid] = w[b * CIN + tid];
    if (tid < 64) msh[tid] = msg[b * 64 + tid];
    __syncthreads();
    int warp = tid >> 5, lane = tid & 31;
    #pragma unroll 1
    for (int ii = 0; ii < 32; ii++) {
        int i = warp * 32 + ii;
        const float* ar = aw + (size_t)i * CIN;
        float acc = 0.f;
        for (int j = lane; j < CIN; j += 32) acc += wsh[j] * ar[j];
        float accm = 0.f;
        for (int m = lane; m < 64; m += 32) accm += msh[m] * msw[m * CIN + i];
        float v = warpReduceSum(acc + 0.01f * accm);
        if (lane == 0) ssh[i] = v + ab[i];
    }
    __syncthreads();
    float sv = ssh[tid];
    float ss = warpReduceSum(sv * sv);
    if (lane == 0) red[warp] = ss;
    __syncthreads();
    if (warp == 0) {
        float t = (lane < 16) ? red[lane] : 0.f;
        t = warpReduceSum(t);
        if (lane == 0) red[0] = t;
    }
    __syncthreads();
    g_sn[b * CIN + tid] = sv * rsqrtf(red[0] * (1.f / CIN));
    float bacc = 0.f;
    #pragma unroll 8
    for (int m = 0; m < 64; m++) bacc += msh[m] * mbw[m * COUT + tid];
    g_bb[b * COUT + tid] = bias[tid] + 0.01f * bacc;
}

// ---------------- K2: weight norms ----------------
__global__ void k2_wnorm(const float* __restrict__ weight) {
    int o = blockIdx.x, tid = threadIdx.x;
    float tot = 0.f;
    for (int i = tid; i < CIN; i += 256) {
        const float* wp = weight + ((size_t)o * CIN + i) * 9;
        float sq = 0.f;
        #pragma unroll
        for (int k = 0; k < 9; k++) sq += wp[k] * wp[k];
        g_rawsq[o * CIN + i] = sq;
        tot += sq;
    }
    __shared__ float red[8];
    int warp = tid >> 5, lane = tid & 31;
    tot = warpReduceSum(tot);
    if (lane == 0) red[warp] = tot;
    __syncthreads();
    if (warp == 0) {
        float t = (lane < 8) ? red[lane] : 0.f;
        t = warpReduceSum(t);
        if (lane == 0) g_wscale[o] = rsqrtf(t * (1.f / (CIN * 9)));
    }
}

// ---------------- K3: demod scale g[b,o] ----------------
__global__ void k3_demod(const float* __restrict__ mag) {
    int o = blockIdx.x, b = blockIdx.y, tid = threadIdx.x;
    float acc = 0.f;
    for (int i = tid; i < CIN; i += 128) {
        float s = g_sn[b * CIN + i];
        acc += g_rawsq[o * CIN + i] * s * s;
    }
    __shared__ float red[4];
    int warp = tid >> 5, lane = tid & 31;
    acc = warpReduceSum(acc);
    if (lane == 0) red[warp] = acc;
    __syncthreads();
    if (tid == 0) {
        float t = red[0] + red[1] + red[2] + red[3];
        float wsc = g_wscale[o];
        float d = rsqrtf(wsc * wsc * t + 1e-8f);
        g_g[b * COUT + o] = d * wsc * rsqrtf(mag[0]);
    }
}

// ---------------- K0x: padded half2(x*sn); 2D grid kills 64-bit div ----
// grid (7, B_*256): p = bx*256+tid (0..1763), mp = by = b*256+pair
__global__ void k0_prex(const float* __restrict__ x) {
    int p = blockIdx.x * 256 + threadIdx.x;
    if (p >= XP_STRIDE) return;
    int mp = blockIdx.y;
    int b = mp >> 8, pairIdx = mp & 255;
    int c0 = pairIdx * 2;
    int prg = p / 42, pc = p - prg * 42;
    int gr = prg - 2, gq = pc - 2;
    float v0 = 0.f, v1 = 0.f;
    if ((unsigned)gr < HS && (unsigned)gq < WS) {
        size_t sidx = (((size_t)b * CIN + c0) * HS + gr) * WS + gq;
        v0 = x[sidx] * g_sn[b * CIN + c0];
        v1 = x[sidx + (size_t)HS * WS] * g_sn[b * CIN + c0 + 1];
    }
    __half2 h = __floats2half2_rn(v0, v1);
    g_xh[(size_t)mp * XP_STRIDE + p] = *(uint32_t*)&h;
}

// ---------------- K0w: weights -> half2 mma layout -------------
__global__ void k0_prew(const float* __restrict__ weight) {
    int e = blockIdx.x * 256 + threadIdx.x;
    const int N = COUT * 256 * 9;      // (o, global pair, tap)
    if (e >= N) return;
    int tap = e % 9;
    int r = e / 9;
    int kp = r & 255;                  // global channel pair 0..255
    int o = r >> 8;
    int chunk = kp >> 3, kpl = kp & 7;
    int kpidx = (kpl & 3) * 2 + (kpl >> 2);
    size_t s0 = ((size_t)o * CIN + kp * 2) * 9 + tap;
    __half2 h = __floats2half2_rn(weight[s0], weight[s0 + 9]);
    size_t dst = ((((size_t)(o >> 6) * 32 + chunk) * 9 + tap) * 512) + (o & 63) * 8 + kpidx;
    g_wh2[dst] = *(uint32_t*)&h;
}

// ---------------- K4: fp16 m16n8k16 conv, cp.async double-buffered ----
// grid = (8 o-tiles, 10 r-tiles of 4 rows, 16 b), block = 128 (4 warps), occ 4
__global__ __launch_bounds__(128, 4) void k4_mma() {
    extern __shared__ uint32_t dsm[];
    const int b  = blockIdx.z;
    const int o0 = blockIdx.x * 64;
    const int r0 = blockIdx.y * 4;

    const int tid  = threadIdx.x;
    const int lane = tid & 31;
    const int wrp  = tid >> 5;
    const int ob   = (wrp & 1) * 32;    // warp o-offset
    const int pr0  = (wrp >> 1) * 2;    // warp row-offset (0,2)
    const int ln4  = lane >> 2;
    const int lk   = lane & 3;

    float c[2][10][4];
    #pragma unroll
    for (int s = 0; s < 2; s++)
        #pragma unroll
        for (int f = 0; f < 10; f++)
            #pragma unroll
            for (int j = 0; j < 4; j++) c[s][f][j] = 0.f;

    const uint32_t* xsrc = g_xh + (size_t)(b * 256) * XP_STRIDE + r0 * 42;
    const uint32_t* wsrc0 = g_wh2 + (size_t)blockIdx.x * 32 * 9 * 512;
    const uint32_t sbase = (uint32_t)__cvta_generic_to_shared(dsm);

    auto issue = [&](int chunk, int stage) {
        const uint32_t xs = sbase + (uint32_t)stage * (STAGE_U * 4);
        const uint32_t wsb = xs + XTILE_U * 4;
        const uint32_t* sx = xsrc + (size_t)chunk * 8 * XP_STRIDE;
        #pragma unroll
        for (int it = 0; it < 4; it++) {
            int e = tid + it * 128;
            if (e < 504) {
                int pr = e / 63, j = e - pr * 63;
                cp_async16(xs + (uint32_t)(pr * XT_S + 4 * j) * 4,
                           sx + (size_t)pr * XP_STRIDE + 4 * j);
            }
        }
        const uint32_t* sw = wsrc0 + (size_t)chunk * (9 * 512);
        #pragma unroll
        for (int it = 0; it < 9; it++) {
            int e = tid + it * 128;
            cp_async16(wsb + (uint32_t)e * 16, sw + (size_t)e * 4);
        }
        asm volatile("cp.async.commit_group;");
    };

    issue(0, 0);
    issue(1, 1);

    for (int i = 0; i < 32; i++) {
        if (i < 30) asm volatile("cp.async.wait_group 1;");
        else        asm volatile("cp.async.wait_group 0;");
        __syncthreads();
        const uint32_t* xsm = dsm + (i & 1) * STAGE_U;
        const uint32_t* wsm = xsm + XTILE_U;

        #pragma unroll
        for (int ky = 0; ky < 3; ky++) {
            #pragma unroll
            for (int kx = 0; kx < 3; kx++) {
                const int tap = ky * 3 + kx;
                uint2 a_lo[2], a_hi[2];
                #pragma unroll
                for (int s = 0; s < 2; s++) {
                    const uint32_t* wp = wsm + tap * 512 + (ob + s * 16 + ln4) * 8 + lk * 2;
                    a_lo[s] = *(const uint2*)wp;          // rows +0: (a0, a2)
                    a_hi[s] = *(const uint2*)(wp + 64);   // rows +8: (a1, a3)
                }
                #pragma unroll
                for (int f = 0; f < 10; f++) {
                    const int pr = pr0 + (f >= 5 ? 1 : 0);
                    const int cg = (f >= 5 ? f - 5 : f);
                    const int idx = (pr + ky) * 42 + cg * 8 + ln4 + kx;
                    uint32_t b0 = xsm[lk * XT_S + idx];
                    uint32_t b1 = xsm[(lk + 4) * XT_S + idx];
                    mma_f16(c[0][f], a_lo[0].x, a_hi[0].x, a_lo[0].y, a_hi[0].y, b0, b1);
                    mma_f16(c[1][f], a_lo[1].x, a_hi[1].x, a_lo[1].y, a_hi[1].y, b0, b1);
                }
            }
        }
        __syncthreads();
        if (i + 2 < 32) issue(i + 2, i & 1);
    }

    const int n0 = lk * 2;
    #pragma unroll
    for (int s = 0; s < 2; s++) {
        #pragma unroll
        for (int rh = 0; rh < 2; rh++) {
            const int o = o0 + ob + s * 16 + ln4 + rh * 8;
            const float gg = g_g[b * COUT + o];
            const float bb = g_bb[b * COUT + o];
            float* abase = g_a + ((size_t)(b * COUT + o)) * (HO * HO);
            #pragma unroll
            for (int f = 0; f < 10; f++) {
                const int r = r0 + pr0 + (f >= 5 ? 1 : 0);
                if (r >= HO) continue;
                const int cg = (f >= 5 ? f - 5 : f);
                const int q = cg * 8 + n0;
                float* ap = abase + r * HO;
                float v0 = c[s][f][rh * 2 + 0] * gg + bb;
                float v1 = c[s][f][rh * 2 + 1] * gg + bb;
                if (q < HO)     ap[q]     = v0;
                if (q + 1 < HO) ap[q + 1] = v1;
            }
        }
    }
}

// ---------------- K5: fused filtered_lrelu (register-windowed) ----------
#define SB_APAD 0
#define SB_VPAD (46 * 38)
#define SB_Z    (46 * 38 + 82 * 46)
#define SB_TOT  (46 * 38 + 82 * 46 + 82 * 82)   // 12244 floats = 48976 B

__global__ __launch_bounds__(256) void k5_flrelu(const float* __restrict__ fup,
                                                 const float* __restrict__ fdn,
                                                 float* __restrict__ out) {
    const int map = blockIdx.x;
    __shared__ float sb[SB_TOT];
    float* Apad = sb + SB_APAD;   // 46 x 38
    float* Vpad = sb + SB_VPAD;   // 82 x 46
    float* Z    = sb + SB_Z;      // 82 x 82
    float* T    = sb;             // 36 x 82 (aliases Apad+Vpad, dead by then)
    const int tid = threadIdx.x;

    float fu[12], fd[12];
    #pragma unroll
    for (int s = 0; s < 12; s++) { fu[s] = fup[s] * 2.f; fd[s] = fdn[s]; }

    for (int i = tid; i < SB_Z; i += 256) sb[i] = 0.f;    // zero Apad+Vpad
    __syncthreads();
    const float* ap = g_a + (size_t)map * HO * HO;
    for (int i = tid; i < HO * HO; i += 256) {
        int r = i / HO, q = i - r * HO;
        Apad[(r + 4) * 38 + q] = ap[i];
    }
    __syncthreads();

    // ---- Vup: 228 threads, j = col, 14 u-rows per thread ----
    if (tid < 228) {
        const int j = tid % 38, ub = tid / 38;
        const int u0 = ub * 14;            // even
        const int a0 = u0 >> 1;
        float win[13];
        #pragma unroll
        for (int i = 0; i < 13; i++)
            win[i] = (a0 + i < 46) ? Apad[(a0 + i) * 38 + j] : 0.f;
        #pragma unroll
        for (int du = 0; du < 14; du++) {
            int u = u0 + du;
            if (u < 82) {
                const int ph = du & 1;
                float acc = 0.f;
                #pragma unroll
                for (int sg = 0; sg < 6; sg++)
                    acc += fu[2 * sg + ph] * win[(du >> 1) + 5 - sg];
                Vpad[u * 46 + (j + 4)] = acc;
            }
        }
    }
    __syncthreads();

    // ---- Hup + lrelu + clamp: 246 threads, u = row, 28 xq per thread ----
    if (tid < 246) {
        const int u = tid % 82, xb = tid / 82;
        const int x0 = xb * 28;            // even
        const int cb = x0 >> 1;
        float win[19];
        #pragma unroll
        for (int i = 0; i < 19; i++)
            win[i] = (cb + i < 46) ? Vpad[u * 46 + cb + i] : 0.f;
        #pragma unroll
        for (int dx = 0; dx < 28; dx++) {
            int xq = x0 + dx;
            if (xq < 82) {
                const int ph = dx & 1;
                float acc = 0.f;
                #pragma unroll
                for (int sg = 0; sg < 6; sg++)
                    acc += fu[2 * sg + ph] * win[(dx >> 1) + 5 - sg];
                acc = (acc >= 0.f) ? acc : 0.2f * acc;
                acc *= 1.4142135623730951f;
                acc = fminf(fmaxf(acc, -256.f), 256.f);
                Z[u * 82 + xq] = acc;
            }
        }
    }
    __syncthreads();

    // ---- Vdown: 246 threads, xq = col, 12 r per thread ----
    if (tid < 246) {
        const int xq = tid % 82, rb = tid / 82;
        const int r0 = rb * 12;
        const int z0 = 2 * r0;
        float wz[34];
        #pragma unroll
        for (int i = 0; i < 34; i++)
            wz[i] = Z[(z0 + i) * 82 + xq];
        #pragma unroll
        for (int dr = 0; dr < 12; dr++) {
            float acc = 0.f;
            #pragma unroll
            for (int s = 0; s < 12; s++)
                acc += fd[s] * wz[2 * dr + 11 - s];
            T[(r0 + dr) * 82 + xq] = acc;
        }
    }
    __syncthreads();

    // ---- Hdown: 216 threads, r = row, 6 c per thread ----
    if (tid < 216) {
        const int r = tid % 36, cbk = tid / 36;
        const int c0 = cbk * 6;
        float wt[22];
        #pragma unroll
        for (int i = 0; i < 22; i++)
            wt[i] = T[r * 82 + 2 * c0 + i];
        float* op = out + (size_t)map * 36 * 36 + r * 36;
        #pragma unroll
        for (int dc = 0; dc < 6; dc++) {
            float acc = 0.f;
            #pragma unroll
            for (int s = 0; s < 12; s++)
                acc += fd[s] * wt[2 * dc + 11 - s];
            op[c0 + dc] = acc;
        }
    }
}

// ---------------- launch ----------------
extern "C" void kernel_launch(void* const* d_in, const int* in_sizes, int n_in,
                              void* d_out, int out_size) {
    const float* x    = (const float*)d_in[0];
    const float* w    = (const float*)d_in[1];
    const float* msg  = (const float*)d_in[2];
    const float* aw   = (const float*)d_in[3];
    const float* ab   = (const float*)d_in[4];
    const float* wgt  = (const float*)d_in[5];
    const float* bias = (const float*)d_in[6];
    const float* msw  = (const float*)d_in[7];
    const float* mbw  = (const float*)d_in[8];
    const float* fup  = (const float*)d_in[9];
    const float* fdn  = (const float*)d_in[10];
    const float* mag  = (const float*)d_in[11];
    float* out = (float*)d_out;

    cudaFuncSetAttribute(k4_mma, cudaFuncAttributeMaxDynamicSharedMemorySize, K4_SMEM);

    k1_style<<<B_, 512>>>(w, msg, aw, ab, bias, msw, mbw);
    k2_wnorm<<<COUT, 256>>>(wgt);
    k3_demod<<<dim3(COUT, B_), 128>>>(mag);
    {
        int nw = COUT * 256 * 9;
        k0_prew<<<(nw + 255) / 256, 256>>>(wgt);
        k0_prex<<<dim3(7, B_ * 256), 256>>>(x);
    }
    k4_mma<<<dim3(8, 10, B_), 128, K4_SMEM>>>();
    k5_flrelu<<<B_ * COUT, 256>>>(fup, fdn, out);
}